// round 13
// baseline (speedup 1.0000x reference)
#include <cuda_runtime.h>
#include <cuda_fp16.h>

#define NB 64
#define NC 64
#define NH 32
#define NW 32
#define NOC 128
#define NL 1024
#define PH 34
#define NCTA 296                      // 2 CTAs per SM

#define SAKH 40                       // A smem row stride (halves), 80 B
#define A_STG_B (64 * SAKH * 2)       // 5120 B  (64 b-rows x 32ch halves + pad)
#define WROW 132                      // W smem row stride (floats), 528 B
#define W_STG_B (32 * WROW * 4)       // 16896 B (32 ch-rows x 128 o floats + pad)
#define STG_B (A_STG_B + W_STG_B)     // 22016 B
#define NSTG 4
#define MBAR_OFF (NSTG * STG_B)       // 88064
#define SMEM_BYTES (MBAR_OFF + 64)

// Scratch: x as fp16, [pixel=(y*34+x)][b][c], border zero.
__device__ __half g_xh[PH * PH * NB * NC];

// ---------------------------------------------------------------------------
__device__ __forceinline__ void cp16(unsigned int s, const void* g) {
    asm volatile("cp.async.cg.shared.global [%0], [%1], 16;" :: "r"(s), "l"(g));
}
__device__ __forceinline__ unsigned int pack_h2(float a, float b) {
    __half2 h = __floats2half2_rn(a, b);
    return *reinterpret_cast<unsigned int*>(&h);
}
__device__ __forceinline__ void mbar_init(unsigned int a, unsigned int c) {
    asm volatile("mbarrier.init.shared.b64 [%0], %1;" :: "r"(a), "r"(c) : "memory");
}
__device__ __forceinline__ void mbar_arrive(unsigned int a) {
    asm volatile("mbarrier.arrive.shared.b64 _, [%0];" :: "r"(a) : "memory");
}
__device__ __forceinline__ void mbar_wait(unsigned int a, int par) {
    asm volatile(
        "{\n\t.reg .pred P;\n\tW%=:\n\t"
        "mbarrier.try_wait.parity.shared.b64 P, [%0], %1, 0x989680;\n\t"
        "@!P bra W%=;\n\t}" :: "r"(a), "r"(par) : "memory");
}

// ---------------------------------------------------------------------------
// Kernel 0: zero the 132 border pixels of g_xh. grid 132 x 128.
// ---------------------------------------------------------------------------
__global__ void __launch_bounds__(128) border_kernel() {
    int bp = blockIdx.x;               // 0..131
    int y, xx;
    if (bp < PH) { y = 0; xx = bp; }                       // top row
    else if (bp < 2 * PH) { y = PH - 1; xx = bp - PH; }    // bottom row
    else if (bp < 2 * PH + NH) { y = bp - 2 * PH + 1; xx = 0; }
    else { y = bp - (2 * PH + NH) + 1; xx = PH - 1; }
    uint4* dst = (uint4*)(g_xh + (size_t)(y * PH + xx) * (NB * NC));
    #pragma unroll
    for (int i = 0; i < 4; ++i)
        dst[threadIdx.x + i * 128] = make_uint4(0, 0, 0, 0);
}

// ---------------------------------------------------------------------------
// Kernel 1: transpose x[b][c][h][w] f32 -> g_xh[(h+1)*34+(w+1)][b][c] fp16.
// grid (32 h, 16 b-groups of 4), 128 thr.
// ---------------------------------------------------------------------------
__global__ void __launch_bounds__(128) transpose_half_kernel(const float* __restrict__ x) {
    __shared__ __half s[4][64][33];
    int h = blockIdx.x;
    int b0 = blockIdx.y * 4;
    int tid = threadIdx.x;
    for (int idx = tid; idx < 4 * 64 * 32; idx += 128) {
        int b = idx >> 11, c = (idx >> 5) & 63, w = idx & 31;
        float v = x[(((size_t)(b0 + b) * NC + c) * NH + h) * NW + w];
        s[b][c][w] = __float2half_rn(v);
    }
    __syncthreads();
    for (int idx = tid; idx < 32 * 4 * 64; idx += 128) {
        int w = idx >> 8, b = (idx >> 6) & 3, c = idx & 63;
        g_xh[((size_t)((h + 1) * PH + (w + 1)) * NB + (b0 + b)) * NC + c] = s[b][c][w];
    }
}

// ---------------------------------------------------------------------------
// Kernel 2: warp-specialized GEMM, 2 CTAs/SM, half-tap stages (K=32).
// 320 thr: warps 0-7 consumers (M half = (wid>>2)*32, OC slice = (wid&3)*32),
// warps 8-9 producers. 4-stage mbarrier ring, lag-3 wait_group.
// ---------------------------------------------------------------------------
__global__ void __launch_bounds__(320, 2) lc_kernel(
    const float* __restrict__ w, const float* __restrict__ bias,
    float* __restrict__ out)
{
    extern __shared__ unsigned char smp[];
    unsigned int sbase = (unsigned int)__cvta_generic_to_shared(smp);
    int tid = threadIdx.x, lane = tid & 31, wid = tid >> 5;

    if (tid == 0) {
        #pragma unroll
        for (int s = 0; s < NSTG; ++s) {
            mbar_init(sbase + MBAR_OFF + s * 16, 2);      // full: 2 producer warps
            mbar_init(sbase + MBAR_OFF + s * 16 + 8, 8);  // empty: 8 consumer warps
        }
    }
    __syncthreads();

    int cta = blockIdx.x;
    int nloc = (cta < 136) ? 4 : 3;            // 136*4 + 160*3 = 1024
    int G = nloc * 18;

    if (wid >= 8) {
        // ===================== PRODUCERS (2 warps) =====================
        int ptid = tid - 256;                  // 0..63
        int loc = 0, seg = 0;
        for (int g = 0; g < G; ++g) {
            int s = g & 3;
            mbar_wait(sbase + MBAR_OFF + s * 16 + 8, ((g >> 2) & 1) ^ 1);
            int l = cta + NCTA * loc;
            int tap = seg >> 1;
            int c0 = (seg & 1) << 5;
            unsigned int aS = sbase + (unsigned)(s * STG_B);
            unsigned int wS = aS + A_STG_B;
            // A: 64 b-rows x 64 B (channels c0..c0+31)
            const char* xs = (const char*)(g_xh +
                (size_t)(((l >> 5) + tap / 3) * PH + (l & 31) + tap % 3) * (NB * NC))
                + c0 * 2;
            #pragma unroll
            for (int f = 0; f < 4; ++f) {
                int idx = ptid + f * 64;
                int r = idx >> 2, j = idx & 3;
                cp16(aS + (unsigned)(r * (SAKH * 2) + j * 16), xs + r * 128 + j * 16);
            }
            // W: 32 ch-rows x 512 B
            #pragma unroll
            for (int f = 0; f < 16; ++f) {
                int idx = ptid + f * 64;
                int r = idx >> 5, j = idx & 31;
                cp16(wS + (unsigned)(r * (WROW * 4) + j * 16),
                     w + ((size_t)((c0 + r) * 9 + tap) * NL + l) * NOC + j * 4);
            }
            asm volatile("cp.async.commit_group;" ::: "memory");
            if (g >= 3) {
                asm volatile("cp.async.wait_group 3;" ::: "memory");
                if (lane == 0) mbar_arrive(sbase + MBAR_OFF + ((g - 3) & 3) * 16);
            }
            if (++seg == 18) { seg = 0; ++loc; }
        }
        asm volatile("cp.async.wait_group 2;" ::: "memory");
        if (lane == 0) mbar_arrive(sbase + MBAR_OFF + ((G - 3) & 3) * 16);
        asm volatile("cp.async.wait_group 1;" ::: "memory");
        if (lane == 0) mbar_arrive(sbase + MBAR_OFF + ((G - 2) & 3) * 16);
        asm volatile("cp.async.wait_group 0;" ::: "memory");
        if (lane == 0) mbar_arrive(sbase + MBAR_OFF + ((G - 1) & 3) * 16);
    } else {
        // ===================== CONSUMERS (8 warps) =====================
        int mbase = (wid >> 2) * 32;
        int obase = (wid & 3) * 32;
        float acc[2][4][4];
        float bz[4][2];
        int loc = 0, seg = 0;
        for (int g = 0; g < G; ++g) {
            int s = g & 3;
            int l = cta + NCTA * loc;
            if (seg == 0) {
                #pragma unroll
                for (int nt = 0; nt < 4; ++nt) {
                    int c0 = obase + nt * 8 + 2 * (lane & 3);
                    bz[nt][0] = __ldg(bias + (size_t)c0 * NL + l);
                    bz[nt][1] = __ldg(bias + (size_t)(c0 + 1) * NL + l);
                    #pragma unroll
                    for (int mt = 0; mt < 2; ++mt)
                        #pragma unroll
                        for (int q = 0; q < 4; ++q) acc[mt][nt][q] = 0.f;
                }
            }
            mbar_wait(sbase + MBAR_OFF + s * 16, (g >> 2) & 1);

            unsigned int aS = sbase + (unsigned)(s * STG_B);
            const float* Bs = (const float*)(smp + s * STG_B + A_STG_B);
            #pragma unroll
            for (int k16 = 0; k16 < 2; ++k16) {
                unsigned int a[2][4], bh[4][2];
                #pragma unroll
                for (int mt = 0; mt < 2; ++mt) {
                    unsigned int addr = aS + (unsigned)(
                        ((mbase + mt * 16 + (lane & 15)) * SAKH
                         + k16 * 16 + ((lane >> 4) << 3)) * 2);
                    asm volatile("ldmatrix.sync.aligned.m8n8.x4.shared.b16 "
                                 "{%0,%1,%2,%3}, [%4];"
                                 : "=r"(a[mt][0]), "=r"(a[mt][1]),
                                   "=r"(a[mt][2]), "=r"(a[mt][3])
                                 : "r"(addr));
                }
                int k0 = k16 * 16 + (lane & 3) * 2;
                #pragma unroll
                for (int nt = 0; nt < 4; ++nt) {
                    int col = obase + nt * 8 + (lane >> 2);
                    bh[nt][0] = pack_h2(Bs[k0 * WROW + col], Bs[(k0 + 1) * WROW + col]);
                    bh[nt][1] = pack_h2(Bs[(k0 + 8) * WROW + col], Bs[(k0 + 9) * WROW + col]);
                }
                #pragma unroll
                for (int mt = 0; mt < 2; ++mt)
                    #pragma unroll
                    for (int nt = 0; nt < 4; ++nt) {
                        asm volatile(
                            "mma.sync.aligned.m16n8k16.row.col.f32.f16.f16.f32 "
                            "{%0,%1,%2,%3}, {%4,%5,%6,%7}, {%8,%9}, {%0,%1,%2,%3};"
                            : "+f"(acc[mt][nt][0]), "+f"(acc[mt][nt][1]),
                              "+f"(acc[mt][nt][2]), "+f"(acc[mt][nt][3])
                            : "r"(a[mt][0]), "r"(a[mt][1]), "r"(a[mt][2]), "r"(a[mt][3]),
                              "r"(bh[nt][0]), "r"(bh[nt][1]));
                    }
            }
            if (lane == 0) mbar_arrive(sbase + MBAR_OFF + s * 16 + 8);

            if (seg == 17) {
                #pragma unroll
                for (int mt = 0; mt < 2; ++mt) {
                    int r0 = mbase + mt * 16 + (lane >> 2);
                    #pragma unroll
                    for (int nt = 0; nt < 4; ++nt) {
                        int c0 = obase + nt * 8 + 2 * (lane & 3);
                        float* p = out + (size_t)r0 * (NOC * NL) + (size_t)c0 * NL + l;
                        p[0]                         = acc[mt][nt][0] + bz[nt][0];
                        p[NL]                        = acc[mt][nt][1] + bz[nt][1];
                        p[(size_t)8 * NOC * NL]      = acc[mt][nt][2] + bz[nt][0];
                        p[(size_t)8 * NOC * NL + NL] = acc[mt][nt][3] + bz[nt][1];
                    }
                }
            }
            if (++seg == 18) { seg = 0; ++loc; }
        }
    }
}

// ---------------------------------------------------------------------------
extern "C" void kernel_launch(void* const* d_in, const int* in_sizes, int n_in,
                              void* d_out, int out_size) {
    const float* x    = (const float*)d_in[0];   // (64,64,32,32)
    const float* wgt  = (const float*)d_in[1];   // (1,576,1024,128)
    const float* bias = (const float*)d_in[2];   // (1,128,32,32)
    float* out = (float*)d_out;                  // (64,128,32,32)

    cudaFuncSetAttribute(lc_kernel,
                         cudaFuncAttributeMaxDynamicSharedMemorySize, SMEM_BYTES);

    border_kernel<<<132, 128>>>();
    transpose_half_kernel<<<dim3(NH, 16), 128>>>(x);
    lc_kernel<<<NCTA, 320, SMEM_BYTES>>>(wgt, bias, out);
}

// round 14
// speedup vs baseline: 1.0530x; 1.0530x over previous
#include <cuda_runtime.h>
#include <cuda_fp16.h>

#define NB 64
#define NC 64
#define NH 32
#define NW 32
#define NOC 128
#define NL 1024
#define PH 34
#define NSMS 148

#define SAKH 72                       // A smem row stride (halves)
#define A_TAP_B (64 * SAKH * 2)       // 9216 B
#define WROW 132                      // W smem row stride (floats)
#define W_TAP_B (64 * WROW * 4)       // 33792 B
#define STG_B (A_TAP_B + W_TAP_B)     // 43008 B
#define NSTG 4
#define MBAR_OFF (NSTG * STG_B)       // 172032
#define SMEM_BYTES (MBAR_OFF + 128)

// Scratch: x as fp16, [pixel=(y*34+x)][b][c], border zero.
__device__ __half g_xh[PH * PH * NB * NC];
__device__ unsigned int g_bar;        // monotonic grid-barrier counter

// ---------------------------------------------------------------------------
__device__ __forceinline__ void cp16(unsigned int s, const void* g) {
    asm volatile("cp.async.cg.shared.global [%0], [%1], 16;" :: "r"(s), "l"(g));
}
__device__ __forceinline__ unsigned int pack_h2(float a, float b) {
    __half2 h = __floats2half2_rn(a, b);
    return *reinterpret_cast<unsigned int*>(&h);
}
__device__ __forceinline__ void mbar_init(unsigned int a, unsigned int c) {
    asm volatile("mbarrier.init.shared.b64 [%0], %1;" :: "r"(a), "r"(c) : "memory");
}
__device__ __forceinline__ void mbar_arrive(unsigned int a) {
    asm volatile("mbarrier.arrive.shared.b64 _, [%0];" :: "r"(a) : "memory");
}
__device__ __forceinline__ void mbar_wait(unsigned int a, int par) {
    asm volatile(
        "{\n\t.reg .pred P;\n\tW%=:\n\t"
        "mbarrier.try_wait.parity.shared.b64 P, [%0], %1;\n\t"
        "@!P bra W%=;\n\t}" :: "r"(a), "r"(par) : "memory");
}

// ---------------------------------------------------------------------------
// Single fused kernel: phase 0 (transpose+border into g_xh), grid barrier,
// phase 1 (warp-specialized per-location GEMM, R7-proven configuration).
// 256 thr: warps 0-3 consumers (each 32 OC, full M=64), warps 4-7 producers.
// Stage = one tap (K=64): A fp16 tile + W f32 tile, 4-stage mbarrier ring.
// ---------------------------------------------------------------------------
__global__ void __launch_bounds__(256, 1) lc_kernel(
    const float* __restrict__ x,
    const float* __restrict__ w, const float* __restrict__ bias,
    float* __restrict__ out)
{
    extern __shared__ unsigned char smp[];
    unsigned int sbase = (unsigned int)__cvta_generic_to_shared(smp);
    int tid = threadIdx.x, lane = tid & 31, wid = tid >> 5;
    int cta = blockIdx.x;

    // mbarriers: FULL(s) = base+MBAR_OFF+s*16, EMPTY(s) = +8
    if (tid == 0) {
        #pragma unroll
        for (int s = 0; s < NSTG; ++s) {
            mbar_init(sbase + MBAR_OFF + s * 16, 4);      // full: 4 producer warps
            mbar_init(sbase + MBAR_OFF + s * 16 + 8, 4);  // empty: 4 consumer warps
        }
    }
    __syncthreads();

    // ================= PHASE 0: build g_xh =================
    // Border zeroing: CTAs 0..131 each zero one border pixel slice (8 KB).
    if (cta < 132) {
        int bp = cta, y, xx;
        if (bp < PH)            { y = 0;       xx = bp; }
        else if (bp < 2 * PH)   { y = PH - 1;  xx = bp - PH; }
        else if (bp < 2 * PH + NH) { y = bp - 2 * PH + 1; xx = 0; }
        else                    { y = bp - (2 * PH + NH) + 1; xx = PH - 1; }
        uint4* dst = (uint4*)(g_xh + (size_t)(y * PH + xx) * (NB * NC));
        #pragma unroll
        for (int i = 0; i < 2; ++i)
            dst[tid + i * 256] = make_uint4(0, 0, 0, 0);
    }
    // Transpose: CTAs 0..127 each do 2 units (unit = one h row x 8 batches).
    if (cta < 128) {
        __half (*s)[64][33] = (__half (*)[64][33])smp;   // 33.8 KB scratch
        #pragma unroll 1
        for (int uu = 0; uu < 2; ++uu) {
            int u = cta * 2 + uu;
            int h = u >> 3, b0 = (u & 7) * 8;
            __syncthreads();
            for (int idx = tid; idx < 8 * 64 * 32; idx += 256) {
                int b = idx >> 11, c = (idx >> 5) & 63, ww = idx & 31;
                float v = x[(((size_t)(b0 + b) * NC + c) * NH + h) * NW + ww];
                s[b][c][ww] = __float2half_rn(v);
            }
            __syncthreads();
            for (int idx = tid; idx < 32 * 8 * 64; idx += 256) {
                int ww = idx >> 9, b = (idx >> 6) & 7, c = idx & 63;
                g_xh[((size_t)((h + 1) * PH + (ww + 1)) * NB + (b0 + b)) * NC + c]
                    = s[b][c][ww];
            }
        }
    }
    // Grid barrier (all 148 CTAs resident: grid == #SMs, 1 CTA/SM).
    __syncthreads();
    if (tid == 0) {
        __threadfence();
        unsigned int t = atomicAdd(&g_bar, 1u);
        unsigned int target = (t / NSMS + 1u) * NSMS;
        while (*((volatile unsigned int*)&g_bar) < target) {}
    }
    __syncthreads();
    __threadfence();

    // ================= PHASE 1: GEMM =================
    int nloc = (cta < 136) ? 7 : 6;            // 136*7 + 12*6 = 1024
    int G = nloc * 9;

    if (wid >= 4) {
        // ===================== PRODUCERS (4 warps) =====================
        int ptid = tid - 128;
        int loc = 0, tap = 0;
        for (int g = 0; g < G; ++g) {
            int s = g & 3;
            mbar_wait(sbase + MBAR_OFF + s * 16 + 8, ((g >> 2) & 1) ^ 1);
            asm volatile("fence.proxy.async.shared::cta;" ::: "memory");
            int l = cta + NSMS * loc;
            unsigned int aS = sbase + (unsigned)(s * STG_B);
            unsigned int wS = aS + A_TAP_B;
            // A: 64 b-rows x 128 B fp16
            const char* xs = (const char*)(g_xh +
                (size_t)(((l >> 5) + tap / 3) * PH + (l & 31) + tap % 3) * (NB * NC));
            #pragma unroll
            for (int f = 0; f < 4; ++f) {
                int idx = ptid + f * 128;
                int r = idx >> 3, j = idx & 7;
                cp16(aS + (unsigned)(r * (SAKH * 2) + j * 16), xs + r * 128 + j * 16);
            }
            // W: 64 ch-rows x 512 B f32
            #pragma unroll
            for (int f = 0; f < 16; ++f) {
                int idx = ptid + f * 128;
                int c = idx >> 5, o4 = idx & 31;
                cp16(wS + (unsigned)(c * (WROW * 4) + o4 * 16),
                     w + ((size_t)(c * 9 + tap) * NL + l) * NOC + o4 * 4);
            }
            asm volatile("cp.async.commit_group;" ::: "memory");
            if (g >= 2) {
                asm volatile("cp.async.wait_group 2;" ::: "memory");
                if (lane == 0) mbar_arrive(sbase + MBAR_OFF + ((g - 2) & 3) * 16);
            }
            if (++tap == 9) { tap = 0; ++loc; }
        }
        asm volatile("cp.async.wait_group 1;" ::: "memory");
        if (lane == 0) mbar_arrive(sbase + MBAR_OFF + ((G - 2) & 3) * 16);
        asm volatile("cp.async.wait_group 0;" ::: "memory");
        if (lane == 0) mbar_arrive(sbase + MBAR_OFF + ((G - 1) & 3) * 16);
    } else {
        // ===================== CONSUMERS (4 warps) =====================
        int obase = wid * 32;
        float acc[4][4][4];
        float bz[4][2];
        int loc = 0, tap = 0;
        for (int g = 0; g < G; ++g) {
            int s = g & 3;
            int l = cta + NSMS * loc;
            if (tap == 0) {
                #pragma unroll
                for (int nt = 0; nt < 4; ++nt) {
                    int c0 = obase + nt * 8 + 2 * (lane & 3);
                    bz[nt][0] = __ldg(bias + (size_t)c0 * NL + l);
                    bz[nt][1] = __ldg(bias + (size_t)(c0 + 1) * NL + l);
                    #pragma unroll
                    for (int mt = 0; mt < 4; ++mt)
                        #pragma unroll
                        for (int q = 0; q < 4; ++q) acc[mt][nt][q] = 0.f;
                }
            }
            mbar_wait(sbase + MBAR_OFF + s * 16, (g >> 2) & 1);

            unsigned int aS = sbase + (unsigned)(s * STG_B);
            const float* Bs = (const float*)(smp + s * STG_B + A_TAP_B);
            #pragma unroll
            for (int k16 = 0; k16 < 4; ++k16) {
                unsigned int a[4][4], bh[4][2];
                #pragma unroll
                for (int mt = 0; mt < 4; ++mt) {
                    unsigned int addr = aS + (unsigned)(
                        ((mt * 16 + (lane & 15)) * SAKH
                         + k16 * 16 + ((lane >> 4) << 3)) * 2);
                    asm volatile("ldmatrix.sync.aligned.m8n8.x4.shared.b16 "
                                 "{%0,%1,%2,%3}, [%4];"
                                 : "=r"(a[mt][0]), "=r"(a[mt][1]),
                                   "=r"(a[mt][2]), "=r"(a[mt][3])
                                 : "r"(addr));
                }
                int k0 = k16 * 16 + (lane & 3) * 2;
                #pragma unroll
                for (int nt = 0; nt < 4; ++nt) {
                    int col = obase + nt * 8 + (lane >> 2);
                    bh[nt][0] = pack_h2(Bs[k0 * WROW + col], Bs[(k0 + 1) * WROW + col]);
                    bh[nt][1] = pack_h2(Bs[(k0 + 8) * WROW + col], Bs[(k0 + 9) * WROW + col]);
                }
                #pragma unroll
                for (int mt = 0; mt < 4; ++mt)
                    #pragma unroll
                    for (int nt = 0; nt < 4; ++nt) {
                        asm volatile(
                            "mma.sync.aligned.m16n8k16.row.col.f32.f16.f16.f32 "
                            "{%0,%1,%2,%3}, {%4,%5,%6,%7}, {%8,%9}, {%0,%1,%2,%3};"
                            : "+f"(acc[mt][nt][0]), "+f"(acc[mt][nt][1]),
                              "+f"(acc[mt][nt][2]), "+f"(acc[mt][nt][3])
                            : "r"(a[mt][0]), "r"(a[mt][1]), "r"(a[mt][2]), "r"(a[mt][3]),
                              "r"(bh[nt][0]), "r"(bh[nt][1]));
                    }
            }
            if (lane == 0) mbar_arrive(sbase + MBAR_OFF + s * 16 + 8);

            if (tap == 8) {
                #pragma unroll
                for (int mt = 0; mt < 4; ++mt) {
                    int r0 = mt * 16 + (lane >> 2);
                    #pragma unroll
                    for (int nt = 0; nt < 4; ++nt) {
                        int c0 = obase + nt * 8 + 2 * (lane & 3);
                        float* p = out + (size_t)r0 * (NOC * NL) + (size_t)c0 * NL + l;
                        p[0]                         = acc[mt][nt][0] + bz[nt][0];
                        p[NL]                        = acc[mt][nt][1] + bz[nt][1];
                        p[(size_t)8 * NOC * NL]      = acc[mt][nt][2] + bz[nt][0];
                        p[(size_t)8 * NOC * NL + NL] = acc[mt][nt][3] + bz[nt][1];
                    }
                }
            }
            if (++tap == 9) { tap = 0; ++loc; }
        }
    }
}

// ---------------------------------------------------------------------------
extern "C" void kernel_launch(void* const* d_in, const int* in_sizes, int n_in,
                              void* d_out, int out_size) {
    const float* x    = (const float*)d_in[0];   // (64,64,32,32)
    const float* wgt  = (const float*)d_in[1];   // (1,576,1024,128)
    const float* bias = (const float*)d_in[2];   // (1,128,32,32)
    float* out = (float*)d_out;                  // (64,128,32,32)

    cudaFuncSetAttribute(lc_kernel,
                         cudaFuncAttributeMaxDynamicSharedMemorySize, SMEM_BYTES);

    lc_kernel<<<NSMS, 256, SMEM_BYTES>>>(x, wgt, bias, out);
}